// round 2
// baseline (speedup 1.0000x reference)
#include <cuda_runtime.h>
#include <math.h>

#define TT   200
#define BB   1024
#define DD   128
#define TOBS 140
#define LL   20
#define LATD 32
#define GU   200
#define UNI  100
#define GIN  168      /* effective K for GRU layer1: y(40) + x(128); ones folded into colsum */
#define ROWS 8
#define NTHR 256
#define NBLK (BB / ROWS)

#define SM_FLOATS 36480

__device__ float g_colsum[3 * GU];

__global__ void colsum_kernel(const float* __restrict__ uw1,
                              const float* __restrict__ rw1,
                              const float* __restrict__ nw1) {
    int j = threadIdx.x;
    const float* w = (blockIdx.x == 0) ? uw1 : (blockIdx.x == 1 ? rw1 : nw1);
    float sacc = 0.f;
    for (int k = GIN; k < 296; ++k) sacc += w[k * GU + j];
    g_colsum[blockIdx.x * GU + j] = sacc;
}

__device__ __forceinline__ void enc_eval(const float* __restrict__ ew1,
                                         const float* __restrict__ eb1,
                                         const float* __restrict__ ew2,
                                         const float* __restrict__ eb2,
                                         const float* __restrict__ ytmp,
                                         float* __restrict__ henc,
                                         float* __restrict__ kbuf, int tid) {
    for (int i = tid; i < ROWS * UNI; i += NTHR) {
        int r = i / UNI, j = i % UNI;
        float a = eb1[j];
#pragma unroll
        for (int k = 0; k < LL; ++k) a += ytmp[r * LL + k] * ew1[k * UNI + j];
        henc[i] = tanhf(a);
    }
    __syncthreads();
    for (int i = tid; i < ROWS * LL; i += NTHR) {
        int r = i / LL, j = i % LL;
        float a = eb2[j];
#pragma unroll 4
        for (int k = 0; k < UNI; ++k) a += henc[r * UNI + k] * ew2[k * LL + j];
        kbuf[i] = a;
    }
}

// GRU layer1 over effective K=168 with 8-row register blocking; W streamed from gmem.
__device__ __forceinline__ void gru_l1_dual(const float* __restrict__ wA,
                                            const float* __restrict__ wB,
                                            const float* __restrict__ ycT,
                                            float initA, float initB,
                                            float* __restrict__ hTA,
                                            float* __restrict__ hTB, int j) {
    float aA[8], aB[8];
#pragma unroll
    for (int r = 0; r < 8; ++r) { aA[r] = initA; aB[r] = initB; }
#pragma unroll 4
    for (int k = 0; k < GIN; ++k) {
        float wa = wA[k * GU + j];
        float wb = wB[k * GU + j];
        float4 y0 = *(const float4*)(ycT + k * 8);
        float4 y1 = *(const float4*)(ycT + k * 8 + 4);
        aA[0] += y0.x * wa; aA[1] += y0.y * wa; aA[2] += y0.z * wa; aA[3] += y0.w * wa;
        aA[4] += y1.x * wa; aA[5] += y1.y * wa; aA[6] += y1.z * wa; aA[7] += y1.w * wa;
        aB[0] += y0.x * wb; aB[1] += y0.y * wb; aB[2] += y0.z * wb; aB[3] += y0.w * wb;
        aB[4] += y1.x * wb; aB[5] += y1.y * wb; aB[6] += y1.z * wb; aB[7] += y1.w * wb;
    }
    float4 o;
    o.x = tanhf(aA[0]); o.y = tanhf(aA[1]); o.z = tanhf(aA[2]); o.w = tanhf(aA[3]);
    *(float4*)(hTA + j * 8) = o;
    o.x = tanhf(aA[4]); o.y = tanhf(aA[5]); o.z = tanhf(aA[6]); o.w = tanhf(aA[7]);
    *(float4*)(hTA + j * 8 + 4) = o;
    o.x = tanhf(aB[0]); o.y = tanhf(aB[1]); o.z = tanhf(aB[2]); o.w = tanhf(aB[3]);
    *(float4*)(hTB + j * 8) = o;
    o.x = tanhf(aB[4]); o.y = tanhf(aB[5]); o.z = tanhf(aB[6]); o.w = tanhf(aB[7]);
    *(float4*)(hTB + j * 8 + 4) = o;
}

__device__ __forceinline__ void gru_l1_single(const float* __restrict__ wA,
                                              const float* __restrict__ ycT,
                                              float initA,
                                              float* __restrict__ hTA, int j) {
    float aA[8];
#pragma unroll
    for (int r = 0; r < 8; ++r) aA[r] = initA;
#pragma unroll 4
    for (int k = 0; k < GIN; ++k) {
        float wa = wA[k * GU + j];
        float4 y0 = *(const float4*)(ycT + k * 8);
        float4 y1 = *(const float4*)(ycT + k * 8 + 4);
        aA[0] += y0.x * wa; aA[1] += y0.y * wa; aA[2] += y0.z * wa; aA[3] += y0.w * wa;
        aA[4] += y1.x * wa; aA[5] += y1.y * wa; aA[6] += y1.z * wa; aA[7] += y1.w * wa;
    }
    float4 o;
    o.x = tanhf(aA[0]); o.y = tanhf(aA[1]); o.z = tanhf(aA[2]); o.w = tanhf(aA[3]);
    *(float4*)(hTA + j * 8) = o;
    o.x = tanhf(aA[4]); o.y = tanhf(aA[5]); o.z = tanhf(aA[6]); o.w = tanhf(aA[7]);
    *(float4*)(hTA + j * 8 + 4) = o;
}

// decoder MLP eval: zin (k-major [32][8]) -> kT (k-major [32][8])
__device__ __forceinline__ void dec_eval(const float* __restrict__ dw1,
                                         const float* __restrict__ db1,
                                         const float* __restrict__ dw2,
                                         const float* __restrict__ db2,
                                         const float* __restrict__ dw3,
                                         const float* __restrict__ db3,
                                         const float* __restrict__ zin,
                                         float* __restrict__ h1T,
                                         float* __restrict__ h2T,
                                         float* __restrict__ kT, int tid) {
    if (tid < UNI) {
        int j = tid;
        float a[8];
#pragma unroll
        for (int r = 0; r < 8; ++r) a[r] = db1[j];
#pragma unroll 4
        for (int k = 0; k < LATD; ++k) {
            float w = dw1[k * UNI + j];
            float4 z0 = *(const float4*)(zin + k * 8);
            float4 z1 = *(const float4*)(zin + k * 8 + 4);
            a[0] += z0.x * w; a[1] += z0.y * w; a[2] += z0.z * w; a[3] += z0.w * w;
            a[4] += z1.x * w; a[5] += z1.y * w; a[6] += z1.z * w; a[7] += z1.w * w;
        }
        float4 o;
        o.x = tanhf(a[0]); o.y = tanhf(a[1]); o.z = tanhf(a[2]); o.w = tanhf(a[3]);
        *(float4*)(h1T + j * 8) = o;
        o.x = tanhf(a[4]); o.y = tanhf(a[5]); o.z = tanhf(a[6]); o.w = tanhf(a[7]);
        *(float4*)(h1T + j * 8 + 4) = o;
    }
    __syncthreads();
    if (tid < UNI) {
        int j = tid;
        float a[8];
#pragma unroll
        for (int r = 0; r < 8; ++r) a[r] = db2[j];
#pragma unroll 4
        for (int k = 0; k < UNI; ++k) {
            float w = dw2[k * UNI + j];
            float4 z0 = *(const float4*)(h1T + k * 8);
            float4 z1 = *(const float4*)(h1T + k * 8 + 4);
            a[0] += z0.x * w; a[1] += z0.y * w; a[2] += z0.z * w; a[3] += z0.w * w;
            a[4] += z1.x * w; a[5] += z1.y * w; a[6] += z1.z * w; a[7] += z1.w * w;
        }
        float4 o;
        o.x = tanhf(a[0]); o.y = tanhf(a[1]); o.z = tanhf(a[2]); o.w = tanhf(a[3]);
        *(float4*)(h2T + j * 8) = o;
        o.x = tanhf(a[4]); o.y = tanhf(a[5]); o.z = tanhf(a[6]); o.w = tanhf(a[7]);
        *(float4*)(h2T + j * 8 + 4) = o;
    }
    __syncthreads();
    {
        int r = tid >> 5, jj = tid & 31;
        float a = db3[jj];
#pragma unroll 4
        for (int k = 0; k < UNI; ++k) a += h2T[k * 8 + r] * dw3[k * LATD + jj];
        kT[jj * 8 + r] = a;
    }
}

extern "C" __global__ void __launch_bounds__(NTHR, 1)
latent_ode_main(const float* __restrict__ truth, const float* __restrict__ tarr,
                const int* __restrict__ obs_idx, const float* __restrict__ eps,
                const float* __restrict__ ew1g, const float* __restrict__ eb1g,
                const float* __restrict__ ew2g, const float* __restrict__ eb2g,
                const float* __restrict__ uw1, const float* __restrict__ ub1g,
                const float* __restrict__ uw2g, const float* __restrict__ ub2g,
                const float* __restrict__ rw1, const float* __restrict__ rb1g,
                const float* __restrict__ rw2g, const float* __restrict__ rb2g,
                const float* __restrict__ nw1, const float* __restrict__ nb1g,
                const float* __restrict__ nw2g, const float* __restrict__ nb2g,
                const float* __restrict__ z0w1, const float* __restrict__ z0b1,
                const float* __restrict__ z0w2, const float* __restrict__ z0b2,
                const float* __restrict__ dw1g, const float* __restrict__ db1g,
                const float* __restrict__ dw2g, const float* __restrict__ db2g,
                const float* __restrict__ dw3g, const float* __restrict__ db3g,
                const float* __restrict__ owg, const float* __restrict__ obg,
                float* __restrict__ out) {
    extern __shared__ float s[];
    const int tid = threadIdx.x;
    const int b0 = blockIdx.x * ROWS;

    float* zT = s;            // 256 floats, persistent across phases
    float* P  = s + 256;

    // ---------------- encoder smem layout ----------------
    float* ew1  = P;            // 2000
    float* eb1  = P + 2000;     // 100
    float* ew2  = P + 2100;     // 2000
    float* eb2  = P + 4100;     // 20
    float* uw2  = P + 4120;     // 8000
    float* rw2  = P + 12120;    // 8000
    float* nw2  = P + 20120;    // 8000
    float* ub1  = P + 28120;    // 200
    float* rb1  = P + 28320;    // 200
    float* nb1  = P + 28520;    // 200
    float* ub2  = P + 28720;    // 40
    float* rb2  = P + 28760;    // 40
    float* nb2  = P + 28800;    // 40
    float* csu  = P + 28840;    // 200
    float* csr  = P + 29040;    // 200
    float* csn  = P + 29240;    // 200
    float* y    = P + 29440;    // 8*40
    float* ycT  = P + 29760;    // 168*8
    float* henc = P + 31104;    // 8*100
    float* hTa  = P + 31904;    // 200*8
    float* hTb  = P + 33504;    // 200*8
    float* u_   = P + 35104;    // 320
    float* r_   = P + 35424;    // 320
    float* ytmp = P + 35744;    // 160
    float* kbuf = P + 35904;    // 160
    float* acc  = P + 36064;    // 160  (end 36224)

    // load encoder-phase weights
    for (int i = tid; i < 2000; i += NTHR) { ew1[i] = ew1g[i]; ew2[i] = ew2g[i]; }
    for (int i = tid; i < 100;  i += NTHR) eb1[i] = eb1g[i];
    for (int i = tid; i < 20;   i += NTHR) eb2[i] = eb2g[i];
    for (int i = tid; i < 8000; i += NTHR) { uw2[i] = uw2g[i]; rw2[i] = rw2g[i]; nw2[i] = nw2g[i]; }
    for (int i = tid; i < 200;  i += NTHR) {
        ub1[i] = ub1g[i]; rb1[i] = rb1g[i]; nb1[i] = nb1g[i];
        csu[i] = g_colsum[i]; csr[i] = g_colsum[200 + i]; csn[i] = g_colsum[400 + i];
    }
    for (int i = tid; i < 40; i += NTHR) { ub2[i] = ub2g[i]; rb2[i] = rb2g[i]; nb2[i] = nb2g[i]; }
    for (int i = tid; i < ROWS * 40; i += NTHR) y[i] = 0.f;
    __syncthreads();

    // ================= encoder scan (reversed observations) =================
    for (int st = 0; st < TOBS; ++st) {
        int io = obs_idx[TOBS - 1 - st];
        float dt = 0.f;
        if (st > 0) { int ip = obs_idx[TOBS - st]; dt = tarr[io] - tarr[ip]; }

        // ---- RK4 on ym ----
        for (int i = tid; i < ROWS * LL; i += NTHR) { int r = i / LL, j = i % LL; ytmp[i] = y[r * 40 + j]; }
        __syncthreads();
        enc_eval(ew1, eb1, ew2, eb2, ytmp, henc, kbuf, tid);
        __syncthreads();
        for (int i = tid; i < ROWS * LL; i += NTHR) {
            int r = i / LL, j = i % LL;
            float k1 = kbuf[i]; acc[i] = k1; ytmp[i] = y[r * 40 + j] + 0.5f * dt * k1;
        }
        __syncthreads();
        enc_eval(ew1, eb1, ew2, eb2, ytmp, henc, kbuf, tid);
        __syncthreads();
        for (int i = tid; i < ROWS * LL; i += NTHR) {
            int r = i / LL, j = i % LL;
            float k2 = kbuf[i]; acc[i] += 2.f * k2; ytmp[i] = y[r * 40 + j] + 0.5f * dt * k2;
        }
        __syncthreads();
        enc_eval(ew1, eb1, ew2, eb2, ytmp, henc, kbuf, tid);
        __syncthreads();
        for (int i = tid; i < ROWS * LL; i += NTHR) {
            int r = i / LL, j = i % LL;
            float k3 = kbuf[i]; acc[i] += 2.f * k3; ytmp[i] = y[r * 40 + j] + dt * k3;
        }
        __syncthreads();
        enc_eval(ew1, eb1, ew2, eb2, ytmp, henc, kbuf, tid);
        __syncthreads();
        for (int i = tid; i < ROWS * LL; i += NTHR) {
            int r = i / LL, j = i % LL;
            y[r * 40 + j] += dt * (1.f / 6.f) * (acc[i] + kbuf[i]);
        }
        __syncthreads();

        // ---- build ycT (k-major, 8 rows contiguous): [y(40), x(128)] ----
        for (int i = tid; i < GIN * ROWS; i += NTHR) {
            int k = i / ROWS, r = i % ROWS;
            ycT[i] = (k < 40) ? y[r * 40 + k]
                              : truth[(size_t)io * (BB * DD) + (size_t)(b0 + r) * DD + (k - 40)];
        }
        __syncthreads();

        // ---- u,r layer1 ----
        if (tid < GU)
            gru_l1_dual(uw1, rw1, ycT, csu[tid] + ub1[tid], csr[tid] + rb1[tid], hTa, hTb, tid);
        __syncthreads();

        // ---- u,r layer2 + sigmoid ----
        for (int i = tid; i < 2 * ROWS * 40; i += NTHR) {
            int g = i / 320, rr = (i / 40) & 7, jj = i % 40;
            const float* hT = g ? hTb : hTa;
            const float* w2 = g ? rw2 : uw2;
            float a = (g ? rb2 : ub2)[jj];
#pragma unroll 4
            for (int k = 0; k < GU; ++k) a += hT[k * 8 + rr] * w2[k * 40 + jj];
            float sg = 1.f / (1.f + expf(-a));
            (g ? r_ : u_)[rr * 40 + jj] = sg;
        }
        __syncthreads();

        // ---- nc: scale y-part of ycT by r ----
        for (int i = tid; i < 40 * ROWS; i += NTHR) {
            int k = i / 8, r = i & 7;
            ycT[i] *= r_[r * 40 + k];
        }
        __syncthreads();

        // ---- n layer1 ----
        if (tid < GU)
            gru_l1_single(nw1, ycT, csn[tid] + nb1[tid], hTa, tid);
        __syncthreads();

        // ---- n layer2 (linear) + state update ----
        for (int i = tid; i < ROWS * 40; i += NTHR) {
            int rr = i / 40, jj = i % 40;
            float a = nb2[jj];
#pragma unroll 4
            for (int k = 0; k < GU; ++k) a += hTa[k * 8 + rr] * nw2[k * 40 + jj];
            float val = (jj < LL) ? a : fabsf(a);
            float uu = u_[i];
            y[i] = (1.f - uu) * val + uu * y[i];
        }
        __syncthreads();
    }

    // ================= z0 head =================
    for (int i = tid; i < ROWS * UNI; i += NTHR) {
        int r = i / UNI, j = i % UNI;
        float a = z0b1[j];
#pragma unroll 4
        for (int k = 0; k < 40; ++k) a += y[r * 40 + k] * z0w1[k * UNI + j];
        henc[i] = tanhf(a);
    }
    __syncthreads();
    for (int i = tid; i < ROWS * 64; i += NTHR) {
        int r = i / 64, j = i % 64;
        float a = z0b2[j];
#pragma unroll 4
        for (int k = 0; k < UNI; ++k) a += henc[r * UNI + k] * z0w2[k * 64 + j];
        hTa[r * 64 + j] = a;
    }
    __syncthreads();
    {
        int r = tid >> 5, j = tid & 31;
        float m = hTa[r * 64 + j];
        float sd = fabsf(hTa[r * 64 + 32 + j]);
        zT[j * 8 + r] = m + eps[(size_t)(b0 + r) * LATD + j] * sd;
    }
    __syncthreads();

    // ---------------- decoder smem layout (aliases P) ----------------
    float* dw1   = P;             // 3200
    float* dw2   = P + 3200;      // 10000
    float* dw3   = P + 13200;     // 3200
    float* db1   = P + 16400;     // 100
    float* db2   = P + 16500;     // 100
    float* db3   = P + 16600;     // 32
    float* ow    = P + 16632;     // 4096
    float* ob    = P + 20728;     // 128
    float* h1T   = P + 20856;     // 800
    float* h2T   = P + 21656;     // 800
    float* ztmpT = P + 22456;     // 256
    float* kT    = P + 22712;     // 256
    float* zacc  = P + 22968;     // 256

    for (int i = tid; i < 3200;  i += NTHR) { dw1[i] = dw1g[i]; dw3[i] = dw3g[i]; }
    for (int i = tid; i < 10000; i += NTHR) dw2[i] = dw2g[i];
    for (int i = tid; i < 100;   i += NTHR) { db1[i] = db1g[i]; db2[i] = db2g[i]; }
    for (int i = tid; i < 32;    i += NTHR) db3[i] = db3g[i];
    for (int i = tid; i < 4096;  i += NTHR) ow[i] = owg[i];
    for (int i = tid; i < 128;   i += NTHR) ob[i] = obg[i];
    __syncthreads();

    // output projection for t = 0
    for (int i = tid; i < ROWS * DD; i += NTHR) {
        int r = i / DD, d = i % DD;
        float a = ob[d];
#pragma unroll
        for (int k = 0; k < LATD; ++k) a += zT[k * 8 + r] * ow[k * DD + d];
        out[(size_t)(b0 + r) * (TT * DD) + d] = a;
    }
    __syncthreads();

    // ================= decoder scan =================
    for (int ti = 1; ti < TT; ++ti) {
        float dt = tarr[ti] - tarr[ti - 1];

        { ztmpT[tid] = zT[tid]; }
        __syncthreads();
        dec_eval(dw1, db1, dw2, db2, dw3, db3, ztmpT, h1T, h2T, kT, tid);
        __syncthreads();
        { float k1 = kT[tid]; zacc[tid] = k1; ztmpT[tid] = zT[tid] + 0.5f * dt * k1; }
        __syncthreads();
        dec_eval(dw1, db1, dw2, db2, dw3, db3, ztmpT, h1T, h2T, kT, tid);
        __syncthreads();
        { float k2 = kT[tid]; zacc[tid] += 2.f * k2; ztmpT[tid] = zT[tid] + 0.5f * dt * k2; }
        __syncthreads();
        dec_eval(dw1, db1, dw2, db2, dw3, db3, ztmpT, h1T, h2T, kT, tid);
        __syncthreads();
        { float k3 = kT[tid]; zacc[tid] += 2.f * k3; ztmpT[tid] = zT[tid] + dt * k3; }
        __syncthreads();
        dec_eval(dw1, db1, dw2, db2, dw3, db3, ztmpT, h1T, h2T, kT, tid);
        __syncthreads();
        { zT[tid] += dt * (1.f / 6.f) * (zacc[tid] + kT[tid]); }
        __syncthreads();

        for (int i = tid; i < ROWS * DD; i += NTHR) {
            int r = i / DD, d = i % DD;
            float a = ob[d];
#pragma unroll
            for (int k = 0; k < LATD; ++k) a += zT[k * 8 + r] * ow[k * DD + d];
            out[(size_t)(b0 + r) * (TT * DD) + (size_t)ti * DD + d] = a;
        }
        __syncthreads();
    }
}

extern "C" void kernel_launch(void* const* d_in, const int* in_sizes, int n_in,
                              void* d_out, int out_size) {
    (void)in_sizes; (void)n_in; (void)out_size;
    const float* truth = (const float*)d_in[0];
    const float* tarr  = (const float*)d_in[1];
    const int*   obs   = (const int*)d_in[2];
    const float* eps   = (const float*)d_in[3];

    size_t smem = (size_t)SM_FLOATS * sizeof(float);
    cudaFuncSetAttribute(latent_ode_main, cudaFuncAttributeMaxDynamicSharedMemorySize, (int)smem);

    colsum_kernel<<<3, GU>>>((const float*)d_in[8], (const float*)d_in[12], (const float*)d_in[16]);

    latent_ode_main<<<NBLK, NTHR, smem>>>(
        truth, tarr, obs, eps,
        (const float*)d_in[4],  (const float*)d_in[5],  (const float*)d_in[6],  (const float*)d_in[7],
        (const float*)d_in[8],  (const float*)d_in[9],  (const float*)d_in[10], (const float*)d_in[11],
        (const float*)d_in[12], (const float*)d_in[13], (const float*)d_in[14], (const float*)d_in[15],
        (const float*)d_in[16], (const float*)d_in[17], (const float*)d_in[18], (const float*)d_in[19],
        (const float*)d_in[20], (const float*)d_in[21], (const float*)d_in[22], (const float*)d_in[23],
        (const float*)d_in[24], (const float*)d_in[25], (const float*)d_in[26], (const float*)d_in[27],
        (const float*)d_in[28], (const float*)d_in[29], (const float*)d_in[30], (const float*)d_in[31],
        (float*)d_out);
}

// round 3
// speedup vs baseline: 1.6890x; 1.6890x over previous
#include <cuda_runtime.h>
#include <math.h>

#define TT   200
#define BB   1024
#define DD   128
#define TOBS 140
#define LL   20
#define LATD 32
#define GU   200
#define UNI  100
#define GIN  168      /* effective K: y(40)+x(128); ones-row folded into colsum */
#define ROWS 8
#define NTHR 256
#define NBLK (BB / ROWS)

#define KT   12
#define NTIL (GIN / KT)   /* 14 */

#define SM_FLOATS 39552

__device__ float g_colsum[3 * GU];

__global__ void colsum_kernel(const float* __restrict__ uw1,
                              const float* __restrict__ rw1,
                              const float* __restrict__ nw1) {
    int j = threadIdx.x;
    const float* w = (blockIdx.x == 0) ? uw1 : (blockIdx.x == 1 ? rw1 : nw1);
    float sacc = 0.f;
    for (int k = GIN; k < 2 * LL + 2 * DD; ++k) sacc += w[k * GU + j];
    g_colsum[blockIdx.x * GU + j] = sacc;
}

// ---- GRU layer1, dual gate (u,r), software-pipelined weight prefetch ----
__device__ __forceinline__ void gru_l1_dual(const float* __restrict__ wA,
                                            const float* __restrict__ wB,
                                            const float* __restrict__ ycT,
                                            float iA, float iB,
                                            float* __restrict__ hTA,
                                            float* __restrict__ hTB, int j) {
    float aA[8], aB[8];
#pragma unroll
    for (int r = 0; r < 8; ++r) { aA[r] = iA; aB[r] = iB; }
    const float* pA = wA + j;
    const float* pB = wB + j;
    float wa[KT], wb[KT];
#pragma unroll
    for (int kk = 0; kk < KT; ++kk) { wa[kk] = pA[kk * GU]; wb[kk] = pB[kk * GU]; }
#pragma unroll 1
    for (int t = 0; t < NTIL; ++t) {
        float na[KT], nb[KT];
        if (t + 1 < NTIL) {
#pragma unroll
            for (int kk = 0; kk < KT; ++kk) {
                na[kk] = pA[((t + 1) * KT + kk) * GU];
                nb[kk] = pB[((t + 1) * KT + kk) * GU];
            }
        }
#pragma unroll
        for (int kk = 0; kk < KT; ++kk) {
            int k = t * KT + kk;
            float4 y0 = *(const float4*)(ycT + k * 8);
            float4 y1 = *(const float4*)(ycT + k * 8 + 4);
            float w0 = wa[kk], w1 = wb[kk];
            aA[0] += y0.x * w0; aA[1] += y0.y * w0; aA[2] += y0.z * w0; aA[3] += y0.w * w0;
            aA[4] += y1.x * w0; aA[5] += y1.y * w0; aA[6] += y1.z * w0; aA[7] += y1.w * w0;
            aB[0] += y0.x * w1; aB[1] += y0.y * w1; aB[2] += y0.z * w1; aB[3] += y0.w * w1;
            aB[4] += y1.x * w1; aB[5] += y1.y * w1; aB[6] += y1.z * w1; aB[7] += y1.w * w1;
        }
        if (t + 1 < NTIL) {
#pragma unroll
            for (int kk = 0; kk < KT; ++kk) { wa[kk] = na[kk]; wb[kk] = nb[kk]; }
        }
    }
    float4 o;
    o.x = tanhf(aA[0]); o.y = tanhf(aA[1]); o.z = tanhf(aA[2]); o.w = tanhf(aA[3]);
    *(float4*)(hTA + j * 8) = o;
    o.x = tanhf(aA[4]); o.y = tanhf(aA[5]); o.z = tanhf(aA[6]); o.w = tanhf(aA[7]);
    *(float4*)(hTA + j * 8 + 4) = o;
    o.x = tanhf(aB[0]); o.y = tanhf(aB[1]); o.z = tanhf(aB[2]); o.w = tanhf(aB[3]);
    *(float4*)(hTB + j * 8) = o;
    o.x = tanhf(aB[4]); o.y = tanhf(aB[5]); o.z = tanhf(aB[6]); o.w = tanhf(aB[7]);
    *(float4*)(hTB + j * 8 + 4) = o;
}

__device__ __forceinline__ void gru_l1_single(const float* __restrict__ wA,
                                              const float* __restrict__ ycT,
                                              float iA,
                                              float* __restrict__ hTA, int j) {
    float aA[8];
#pragma unroll
    for (int r = 0; r < 8; ++r) aA[r] = iA;
    const float* pA = wA + j;
    float wa[KT];
#pragma unroll
    for (int kk = 0; kk < KT; ++kk) wa[kk] = pA[kk * GU];
#pragma unroll 1
    for (int t = 0; t < NTIL; ++t) {
        float na[KT];
        if (t + 1 < NTIL) {
#pragma unroll
            for (int kk = 0; kk < KT; ++kk) na[kk] = pA[((t + 1) * KT + kk) * GU];
        }
#pragma unroll
        for (int kk = 0; kk < KT; ++kk) {
            int k = t * KT + kk;
            float4 y0 = *(const float4*)(ycT + k * 8);
            float4 y1 = *(const float4*)(ycT + k * 8 + 4);
            float w0 = wa[kk];
            aA[0] += y0.x * w0; aA[1] += y0.y * w0; aA[2] += y0.z * w0; aA[3] += y0.w * w0;
            aA[4] += y1.x * w0; aA[5] += y1.y * w0; aA[6] += y1.z * w0; aA[7] += y1.w * w0;
        }
        if (t + 1 < NTIL) {
#pragma unroll
            for (int kk = 0; kk < KT; ++kk) wa[kk] = na[kk];
        }
    }
    float4 o;
    o.x = tanhf(aA[0]); o.y = tanhf(aA[1]); o.z = tanhf(aA[2]); o.w = tanhf(aA[3]);
    *(float4*)(hTA + j * 8) = o;
    o.x = tanhf(aA[4]); o.y = tanhf(aA[5]); o.z = tanhf(aA[6]); o.w = tanhf(aA[7]);
    *(float4*)(hTA + j * 8 + 4) = o;
}

// encoder MLP: ytmpT [20][8] k-major -> partials pe [4][20][8]; internal syncs
__device__ __forceinline__ void enc_eval(const float* __restrict__ ew1,
                                         const float* __restrict__ eb1,
                                         const float* __restrict__ ew2,
                                         const float* __restrict__ ytmpT,
                                         float* __restrict__ hencT,
                                         float* __restrict__ pe, int tid) {
    if (tid < UNI) {
        int j = tid;
        float a[8];
        float b = eb1[j];
#pragma unroll
        for (int r = 0; r < 8; ++r) a[r] = b;
#pragma unroll
        for (int k = 0; k < LL; ++k) {
            float w = ew1[k * UNI + j];
            float4 y0 = *(const float4*)(ytmpT + k * 8);
            float4 y1 = *(const float4*)(ytmpT + k * 8 + 4);
            a[0] += y0.x * w; a[1] += y0.y * w; a[2] += y0.z * w; a[3] += y0.w * w;
            a[4] += y1.x * w; a[5] += y1.y * w; a[6] += y1.z * w; a[7] += y1.w * w;
        }
        float4 o;
        o.x = tanhf(a[0]); o.y = tanhf(a[1]); o.z = tanhf(a[2]); o.w = tanhf(a[3]);
        *(float4*)(hencT + j * 8) = o;
        o.x = tanhf(a[4]); o.y = tanhf(a[5]); o.z = tanhf(a[6]); o.w = tanhf(a[7]);
        *(float4*)(hencT + j * 8 + 4) = o;
    }
    __syncthreads();
    if (tid < 80) {
        int jj = tid % LL, ks = tid / LL;
        float a[8];
#pragma unroll
        for (int r = 0; r < 8; ++r) a[r] = 0.f;
#pragma unroll 5
        for (int k = ks * 25; k < ks * 25 + 25; ++k) {
            float w = ew2[k * LL + jj];
            float4 y0 = *(const float4*)(hencT + k * 8);
            float4 y1 = *(const float4*)(hencT + k * 8 + 4);
            a[0] += y0.x * w; a[1] += y0.y * w; a[2] += y0.z * w; a[3] += y0.w * w;
            a[4] += y1.x * w; a[5] += y1.y * w; a[6] += y1.z * w; a[7] += y1.w * w;
        }
        float* p = pe + ks * 160 + jj * 8;
        *(float4*)p       = make_float4(a[0], a[1], a[2], a[3]);
        *(float4*)(p + 4) = make_float4(a[4], a[5], a[6], a[7]);
    }
    __syncthreads();
}

// decoder MLP partials: zin [32][8] -> pd3 [4][32][8]; internal syncs
__device__ __forceinline__ void dec_eval(const float* __restrict__ dw1,
                                         const float* __restrict__ db1,
                                         const float* __restrict__ dw2,
                                         const float* __restrict__ db2,
                                         const float* __restrict__ dw3,
                                         const float* __restrict__ zin,
                                         float* __restrict__ h1T,
                                         float* __restrict__ h2T,
                                         float* __restrict__ pd1,
                                         float* __restrict__ pd2,
                                         float* __restrict__ pd3, int tid) {
    if (tid < 200) {
        int j = tid % UNI, ks = tid / UNI;
        float a[8];
#pragma unroll
        for (int r = 0; r < 8; ++r) a[r] = 0.f;
#pragma unroll
        for (int k = ks * 16; k < ks * 16 + 16; ++k) {
            float w = dw1[k * UNI + j];
            float4 z0 = *(const float4*)(zin + k * 8);
            float4 z1 = *(const float4*)(zin + k * 8 + 4);
            a[0] += z0.x * w; a[1] += z0.y * w; a[2] += z0.z * w; a[3] += z0.w * w;
            a[4] += z1.x * w; a[5] += z1.y * w; a[6] += z1.z * w; a[7] += z1.w * w;
        }
        float* p = pd1 + ks * 800 + j * 8;
        *(float4*)p       = make_float4(a[0], a[1], a[2], a[3]);
        *(float4*)(p + 4) = make_float4(a[4], a[5], a[6], a[7]);
    }
    __syncthreads();
    for (int i = tid; i < 800; i += NTHR) {
        int j = i >> 3;
        h1T[i] = tanhf(pd1[i] + pd1[800 + i] + db1[j]);
    }
    __syncthreads();
    if (tid < 200) {
        int j = tid % UNI, ks = tid / UNI;
        float a[8];
#pragma unroll
        for (int r = 0; r < 8; ++r) a[r] = 0.f;
#pragma unroll 10
        for (int k = ks * 50; k < ks * 50 + 50; ++k) {
            float w = dw2[k * UNI + j];
            float4 z0 = *(const float4*)(h1T + k * 8);
            float4 z1 = *(const float4*)(h1T + k * 8 + 4);
            a[0] += z0.x * w; a[1] += z0.y * w; a[2] += z0.z * w; a[3] += z0.w * w;
            a[4] += z1.x * w; a[5] += z1.y * w; a[6] += z1.z * w; a[7] += z1.w * w;
        }
        float* p = pd2 + ks * 800 + j * 8;
        *(float4*)p       = make_float4(a[0], a[1], a[2], a[3]);
        *(float4*)(p + 4) = make_float4(a[4], a[5], a[6], a[7]);
    }
    __syncthreads();
    for (int i = tid; i < 800; i += NTHR) {
        int j = i >> 3;
        h2T[i] = tanhf(pd2[i] + pd2[800 + i] + db2[j]);
    }
    __syncthreads();
    if (tid < 128) {
        int jj = tid % LATD, ks = tid / LATD;
        float a[8];
#pragma unroll
        for (int r = 0; r < 8; ++r) a[r] = 0.f;
#pragma unroll 5
        for (int k = ks * 25; k < ks * 25 + 25; ++k) {
            float w = dw3[k * LATD + jj];
            float4 z0 = *(const float4*)(h2T + k * 8);
            float4 z1 = *(const float4*)(h2T + k * 8 + 4);
            a[0] += z0.x * w; a[1] += z0.y * w; a[2] += z0.z * w; a[3] += z0.w * w;
            a[4] += z1.x * w; a[5] += z1.y * w; a[6] += z1.z * w; a[7] += z1.w * w;
        }
        float* p = pd3 + ks * 256 + jj * 8;
        *(float4*)p       = make_float4(a[0], a[1], a[2], a[3]);
        *(float4*)(p + 4) = make_float4(a[4], a[5], a[6], a[7]);
    }
    __syncthreads();
}

extern "C" __global__ void __launch_bounds__(NTHR, 1)
latent_ode_main(const float* __restrict__ truth, const float* __restrict__ tarr,
                const int* __restrict__ obs_idx, const float* __restrict__ eps,
                const float* __restrict__ ew1g, const float* __restrict__ eb1g,
                const float* __restrict__ ew2g, const float* __restrict__ eb2g,
                const float* __restrict__ uw1, const float* __restrict__ ub1g,
                const float* __restrict__ uw2g, const float* __restrict__ ub2g,
                const float* __restrict__ rw1, const float* __restrict__ rb1g,
                const float* __restrict__ rw2g, const float* __restrict__ rb2g,
                const float* __restrict__ nw1, const float* __restrict__ nb1g,
                const float* __restrict__ nw2g, const float* __restrict__ nb2g,
                const float* __restrict__ z0w1, const float* __restrict__ z0b1,
                const float* __restrict__ z0w2, const float* __restrict__ z0b2,
                const float* __restrict__ dw1g, const float* __restrict__ db1g,
                const float* __restrict__ dw2g, const float* __restrict__ db2g,
                const float* __restrict__ dw3g, const float* __restrict__ db3g,
                const float* __restrict__ owg, const float* __restrict__ obg,
                float* __restrict__ out) {
    extern __shared__ float s[];
    const int tid = threadIdx.x;
    const int b0 = blockIdx.x * ROWS;

    float* zT = s;           // [32][8] k-major, persistent
    float* P  = s + 256;

    // ---------------- encoder smem layout ----------------
    float* ew1   = P;            // 2000
    float* ew2   = P + 2000;     // 2000
    float* eb1   = P + 4000;     // 100
    float* eb2   = P + 4100;     // 20 (pad to 4128)
    float* uw2   = P + 4128;     // 8000
    float* rw2   = P + 12128;    // 8000
    float* nw2   = P + 20128;    // 8000
    float* ub1   = P + 28128;    // 200
    float* rb1   = P + 28328;    // 200
    float* nb1   = P + 28528;    // 200
    float* ub2   = P + 28728;    // 40
    float* rb2   = P + 28768;    // 40
    float* nb2   = P + 28808;    // 40
    float* csu   = P + 28848;    // 200
    float* csr   = P + 29048;    // 200
    float* csn   = P + 29248;    // 200
    float* y     = P + 29448;    // 320  row-major [8][40]
    float* ycT   = P + 29768;    // 1344 k-major [168][8]
    float* ytmpT = P + 31112;    // 160  [20][8]
    float* accT  = P + 31272;    // 160
    float* hencT = P + 31432;    // 800  [100][8]
    float* pe    = P + 32232;    // 640  [4][20][8]
    float* hTa   = P + 32872;    // 1600 [200][8]
    float* hTb   = P + 34472;    // 1600
    float* p2    = P + 36072;    // 1280 [2 gates][2 halves][40][8]
    float* pn    = P + 37352;    // 1280 [4][40][8]
    float* u_    = P + 38632;    // 320  [8][40]
    float* r_    = P + 38952;    // 320

    for (int i = tid; i < 2000; i += NTHR) { ew1[i] = ew1g[i]; ew2[i] = ew2g[i]; }
    for (int i = tid; i < 100;  i += NTHR) eb1[i] = eb1g[i];
    for (int i = tid; i < 20;   i += NTHR) eb2[i] = eb2g[i];
    for (int i = tid; i < 8000; i += NTHR) { uw2[i] = uw2g[i]; rw2[i] = rw2g[i]; nw2[i] = nw2g[i]; }
    for (int i = tid; i < 200;  i += NTHR) {
        ub1[i] = ub1g[i]; rb1[i] = rb1g[i]; nb1[i] = nb1g[i];
        csu[i] = g_colsum[i]; csr[i] = g_colsum[200 + i]; csn[i] = g_colsum[400 + i];
    }
    for (int i = tid; i < 40; i += NTHR) { ub2[i] = ub2g[i]; rb2[i] = rb2g[i]; nb2[i] = nb2g[i]; }
    for (int i = tid; i < ROWS * 40; i += NTHR) y[i] = 0.f;
    __syncthreads();

    // ================= encoder scan =================
    for (int st = 0; st < TOBS; ++st) {
        int io = obs_idx[TOBS - 1 - st];
        float dt = 0.f;
        if (st > 0) { int ip = obs_idx[TOBS - st]; dt = tarr[io] - tarr[ip]; }

        // ---- RK4 on ym ----
        for (int i = tid; i < 160; i += NTHR) { int j = i >> 3, r = i & 7; ytmpT[i] = y[r * 40 + j]; }
        __syncthreads();
        enc_eval(ew1, eb1, ew2, ytmpT, hencT, pe, tid);
        if (tid < 160) {
            int j = tid >> 3, r = tid & 7;
            float kv = pe[tid] + pe[160 + tid] + pe[320 + tid] + pe[480 + tid] + eb2[j];
            accT[tid] = kv;
            ytmpT[tid] = y[r * 40 + j] + 0.5f * dt * kv;
        }
        __syncthreads();
        enc_eval(ew1, eb1, ew2, ytmpT, hencT, pe, tid);
        if (tid < 160) {
            int j = tid >> 3, r = tid & 7;
            float kv = pe[tid] + pe[160 + tid] + pe[320 + tid] + pe[480 + tid] + eb2[j];
            accT[tid] += 2.f * kv;
            ytmpT[tid] = y[r * 40 + j] + 0.5f * dt * kv;
        }
        __syncthreads();
        enc_eval(ew1, eb1, ew2, ytmpT, hencT, pe, tid);
        if (tid < 160) {
            int j = tid >> 3, r = tid & 7;
            float kv = pe[tid] + pe[160 + tid] + pe[320 + tid] + pe[480 + tid] + eb2[j];
            accT[tid] += 2.f * kv;
            ytmpT[tid] = y[r * 40 + j] + dt * kv;
        }
        __syncthreads();
        enc_eval(ew1, eb1, ew2, ytmpT, hencT, pe, tid);
        if (tid < 160) {
            int j = tid >> 3, r = tid & 7;
            float kv = pe[tid] + pe[160 + tid] + pe[320 + tid] + pe[480 + tid] + eb2[j];
            y[r * 40 + j] += dt * (1.f / 6.f) * (accT[tid] + kv);
        }
        __syncthreads();

        // ---- build ycT ----
        for (int i = tid; i < GIN * ROWS; i += NTHR) {
            int k = i >> 3, r = i & 7;
            ycT[i] = (k < 40) ? y[r * 40 + k]
                              : truth[(size_t)io * (BB * DD) + (size_t)(b0 + r) * DD + (k - 40)];
        }
        __syncthreads();

        // ---- u,r layer1 ----
        if (tid < GU)
            gru_l1_dual(uw1, rw1, ycT, csu[tid] + ub1[tid], csr[tid] + rb1[tid], hTa, hTb, tid);
        __syncthreads();

        // ---- u,r layer2 (K-split 2) ----
        if (tid < 160) {
            int jj = tid % 40, half = (tid / 40) & 1, g = tid / 80;
            const float* hT = g ? hTb : hTa;
            const float* w2 = g ? rw2 : uw2;
            float a[8];
#pragma unroll
            for (int r = 0; r < 8; ++r) a[r] = 0.f;
#pragma unroll 10
            for (int k = half * 100; k < half * 100 + 100; ++k) {
                float w = w2[k * 40 + jj];
                float4 h0 = *(const float4*)(hT + k * 8);
                float4 h1 = *(const float4*)(hT + k * 8 + 4);
                a[0] += h0.x * w; a[1] += h0.y * w; a[2] += h0.z * w; a[3] += h0.w * w;
                a[4] += h1.x * w; a[5] += h1.y * w; a[6] += h1.z * w; a[7] += h1.w * w;
            }
            float* p = p2 + g * 640 + half * 320 + jj * 8;
            *(float4*)p       = make_float4(a[0], a[1], a[2], a[3]);
            *(float4*)(p + 4) = make_float4(a[4], a[5], a[6], a[7]);
        }
        __syncthreads();
        // reduce + sigmoid
        for (int i = tid; i < 640; i += NTHR) {
            int g = i / 320, rem = i % 320, jj = rem >> 3, r = rem & 7;
            float a = p2[g * 640 + rem] + p2[g * 640 + 320 + rem] + (g ? rb2 : ub2)[jj];
            float sg = 1.f / (1.f + expf(-a));
            (g ? r_ : u_)[r * 40 + jj] = sg;
        }
        __syncthreads();

        // ---- scale y-part of ycT by r ----
        for (int i = tid; i < 320; i += NTHR) {
            int k = i >> 3, r = i & 7;
            ycT[i] *= r_[r * 40 + k];
        }
        __syncthreads();

        // ---- n layer1 ----
        if (tid < GU)
            gru_l1_single(nw1, ycT, csn[tid] + nb1[tid], hTa, tid);
        __syncthreads();

        // ---- n layer2 (K-split 4) ----
        if (tid < 160) {
            int jj = tid % 40, ks = tid / 40;
            float a[8];
#pragma unroll
            for (int r = 0; r < 8; ++r) a[r] = 0.f;
#pragma unroll 10
            for (int k = ks * 50; k < ks * 50 + 50; ++k) {
                float w = nw2[k * 40 + jj];
                float4 h0 = *(const float4*)(hTa + k * 8);
                float4 h1 = *(const float4*)(hTa + k * 8 + 4);
                a[0] += h0.x * w; a[1] += h0.y * w; a[2] += h0.z * w; a[3] += h0.w * w;
                a[4] += h1.x * w; a[5] += h1.y * w; a[6] += h1.z * w; a[7] += h1.w * w;
            }
            float* p = pn + ks * 320 + jj * 8;
            *(float4*)p       = make_float4(a[0], a[1], a[2], a[3]);
            *(float4*)(p + 4) = make_float4(a[4], a[5], a[6], a[7]);
        }
        __syncthreads();
        // reduce + state update
        for (int i = tid; i < 320; i += NTHR) {
            int jj = i >> 3, r = i & 7;
            float a = pn[i] + pn[320 + i] + pn[640 + i] + pn[960 + i] + nb2[jj];
            float val = (jj < LL) ? a : fabsf(a);
            float uu = u_[r * 40 + jj];
            y[r * 40 + jj] = (1.f - uu) * val + uu * y[r * 40 + jj];
        }
        __syncthreads();
    }

    // ================= z0 head (once) =================
    for (int i = tid; i < ROWS * UNI; i += NTHR) {
        int r = i / UNI, j = i % UNI;
        float a = z0b1[j];
#pragma unroll 4
        for (int k = 0; k < 40; ++k) a += y[r * 40 + k] * z0w1[k * UNI + j];
        hencT[i] = tanhf(a);
    }
    __syncthreads();
    for (int i = tid; i < ROWS * 64; i += NTHR) {
        int r = i / 64, j = i % 64;
        float a = z0b2[j];
#pragma unroll 4
        for (int k = 0; k < UNI; ++k) a += hencT[r * UNI + k] * z0w2[k * 64 + j];
        hTa[r * 64 + j] = a;
    }
    __syncthreads();
    {
        int r = tid >> 5, j = tid & 31;
        float m = hTa[r * 64 + j];
        float sd = fabsf(hTa[r * 64 + 32 + j]);
        zT[j * 8 + r] = m + eps[(size_t)(b0 + r) * LATD + j] * sd;
    }
    __syncthreads();

    // ---------------- decoder smem layout (aliases P) ----------------
    float* dw1   = P;             // 3200
    float* dw2   = P + 3200;      // 10000
    float* dw3   = P + 13200;     // 3200
    float* db1   = P + 16400;     // 100
    float* db2   = P + 16500;     // 100
    float* db3   = P + 16600;     // 32
    float* ow    = P + 16632;     // 4096
    float* ob    = P + 20728;     // 128
    float* h1T   = P + 20856;     // 800
    float* h2T   = P + 21656;     // 800
    float* ztmpT = P + 22456;     // 256
    float* zacc  = P + 22712;     // 256
    float* pd1   = P + 22968;     // 1600
    float* pd2   = P + 24568;     // 1600
    float* pd3   = P + 26168;     // 1024

    for (int i = tid; i < 3200;  i += NTHR) { dw1[i] = dw1g[i]; dw3[i] = dw3g[i]; }
    for (int i = tid; i < 10000; i += NTHR) dw2[i] = dw2g[i];
    for (int i = tid; i < 100;   i += NTHR) { db1[i] = db1g[i]; db2[i] = db2g[i]; }
    for (int i = tid; i < 32;    i += NTHR) db3[i] = db3g[i];
    for (int i = tid; i < 4096;  i += NTHR) ow[i] = owg[i];
    for (int i = tid; i < 128;   i += NTHR) ob[i] = obg[i];
    __syncthreads();

    // output projection for t = 0 (register-blocked over 8 rows)
    if (tid < DD) {
        int d = tid;
        float a[8];
        float b = ob[d];
#pragma unroll
        for (int r = 0; r < 8; ++r) a[r] = b;
#pragma unroll
        for (int k = 0; k < LATD; ++k) {
            float w = ow[k * DD + d];
            float4 z0 = *(const float4*)(zT + k * 8);
            float4 z1 = *(const float4*)(zT + k * 8 + 4);
            a[0] += z0.x * w; a[1] += z0.y * w; a[2] += z0.z * w; a[3] += z0.w * w;
            a[4] += z1.x * w; a[5] += z1.y * w; a[6] += z1.z * w; a[7] += z1.w * w;
        }
#pragma unroll
        for (int r = 0; r < 8; ++r)
            out[(size_t)(b0 + r) * (TT * DD) + d] = a[r];
    }
    __syncthreads();

    // ================= decoder scan =================
    for (int ti = 1; ti < TT; ++ti) {
        float dt = tarr[ti] - tarr[ti - 1];

        ztmpT[tid] = zT[tid];
        __syncthreads();
        dec_eval(dw1, db1, dw2, db2, dw3, ztmpT, h1T, h2T, pd1, pd2, pd3, tid);
        {
            int jj = tid >> 3;
            float kv = pd3[tid] + pd3[256 + tid] + pd3[512 + tid] + pd3[768 + tid] + db3[jj];
            zacc[tid] = kv;
            ztmpT[tid] = zT[tid] + 0.5f * dt * kv;
        }
        __syncthreads();
        dec_eval(dw1, db1, dw2, db2, dw3, ztmpT, h1T, h2T, pd1, pd2, pd3, tid);
        {
            int jj = tid >> 3;
            float kv = pd3[tid] + pd3[256 + tid] + pd3[512 + tid] + pd3[768 + tid] + db3[jj];
            zacc[tid] += 2.f * kv;
            ztmpT[tid] = zT[tid] + 0.5f * dt * kv;
        }
        __syncthreads();
        dec_eval(dw1, db1, dw2, db2, dw3, ztmpT, h1T, h2T, pd1, pd2, pd3, tid);
        {
            int jj = tid >> 3;
            float kv = pd3[tid] + pd3[256 + tid] + pd3[512 + tid] + pd3[768 + tid] + db3[jj];
            zacc[tid] += 2.f * kv;
            ztmpT[tid] = zT[tid] + dt * kv;
        }
        __syncthreads();
        dec_eval(dw1, db1, dw2, db2, dw3, ztmpT, h1T, h2T, pd1, pd2, pd3, tid);
        {
            int jj = tid >> 3;
            float kv = pd3[tid] + pd3[256 + tid] + pd3[512 + tid] + pd3[768 + tid] + db3[jj];
            zT[tid] += dt * (1.f / 6.f) * (zacc[tid] + kv);
        }
        __syncthreads();

        // output projection
        if (tid < DD) {
            int d = tid;
            float a[8];
            float b = ob[d];
#pragma unroll
            for (int r = 0; r < 8; ++r) a[r] = b;
#pragma unroll
            for (int k = 0; k < LATD; ++k) {
                float w = ow[k * DD + d];
                float4 z0 = *(const float4*)(zT + k * 8);
                float4 z1 = *(const float4*)(zT + k * 8 + 4);
                a[0] += z0.x * w; a[1] += z0.y * w; a[2] += z0.z * w; a[3] += z0.w * w;
                a[4] += z1.x * w; a[5] += z1.y * w; a[6] += z1.z * w; a[7] += z1.w * w;
            }
#pragma unroll
            for (int r = 0; r < 8; ++r)
                out[(size_t)(b0 + r) * (TT * DD) + (size_t)ti * DD + d] = a[r];
        }
        __syncthreads();
    }
}

extern "C" void kernel_launch(void* const* d_in, const int* in_sizes, int n_in,
                              void* d_out, int out_size) {
    (void)in_sizes; (void)n_in; (void)out_size;
    size_t smem = (size_t)SM_FLOATS * sizeof(float);
    cudaFuncSetAttribute(latent_ode_main, cudaFuncAttributeMaxDynamicSharedMemorySize, (int)smem);

    colsum_kernel<<<3, GU>>>((const float*)d_in[8], (const float*)d_in[12], (const float*)d_in[16]);

    latent_ode_main<<<NBLK, NTHR, smem>>>(
        (const float*)d_in[0], (const float*)d_in[1], (const int*)d_in[2], (const float*)d_in[3],
        (const float*)d_in[4],  (const float*)d_in[5],  (const float*)d_in[6],  (const float*)d_in[7],
        (const float*)d_in[8],  (const float*)d_in[9],  (const float*)d_in[10], (const float*)d_in[11],
        (const float*)d_in[12], (const float*)d_in[13], (const float*)d_in[14], (const float*)d_in[15],
        (const float*)d_in[16], (const float*)d_in[17], (const float*)d_in[18], (const float*)d_in[19],
        (const float*)d_in[20], (const float*)d_in[21], (const float*)d_in[22], (const float*)d_in[23],
        (const float*)d_in[24], (const float*)d_in[25], (const float*)d_in[26], (const float*)d_in[27],
        (const float*)d_in[28], (const float*)d_in[29], (const float*)d_in[30], (const float*)d_in[31],
        (float*)d_out);
}

// round 4
// speedup vs baseline: 1.9334x; 1.1447x over previous
#include <cuda_runtime.h>
#include <math.h>

#define TT   200
#define BB   1024
#define DD   128
#define TOBS 140
#define LL   20
#define LATD 32
#define GU   200
#define UNI  100
#define GIN  168      /* effective K: y(40)+x(128); ones-row folded into colsum */
#define ROWS 8
#define NTHR 512
#define NBLK (BB / ROWS)

#define KH   84       /* K per half for GRU l1 */

#define SM_FLOATS 51048

__device__ float g_colsum[3 * GU];

__global__ void colsum_kernel(const float* __restrict__ uw1,
                              const float* __restrict__ rw1,
                              const float* __restrict__ nw1) {
    int j = threadIdx.x;
    const float* w = (blockIdx.x == 0) ? uw1 : (blockIdx.x == 1 ? rw1 : nw1);
    float sacc = 0.f;
    for (int k = GIN; k < 2 * LL + 2 * DD; ++k) sacc += w[k * GU + j];
    g_colsum[blockIdx.x * GU + j] = sacc;
}

// ---- GRU layer1, dual gate (u,r), K-split half, pipelined weight prefetch ----
__device__ __forceinline__ void gru_l1_dual_ks(const float* __restrict__ wA,
                                               const float* __restrict__ wB,
                                               const float* __restrict__ ycT,
                                               float* __restrict__ pU,
                                               float* __restrict__ pR,
                                               int j, int ks) {
    float aA[8], aB[8];
#pragma unroll
    for (int r = 0; r < 8; ++r) { aA[r] = 0.f; aB[r] = 0.f; }
    const float* pA = wA + (size_t)ks * KH * GU + j;
    const float* pB = wB + (size_t)ks * KH * GU + j;
    const float* yc = ycT + ks * KH * 8;
    float wa[6], wb[6];
#pragma unroll
    for (int kk = 0; kk < 6; ++kk) { wa[kk] = pA[kk * GU]; wb[kk] = pB[kk * GU]; }
#pragma unroll 1
    for (int t = 0; t < 14; ++t) {
        float na[6], nb[6];
        if (t + 1 < 14) {
#pragma unroll
            for (int kk = 0; kk < 6; ++kk) {
                na[kk] = pA[((t + 1) * 6 + kk) * GU];
                nb[kk] = pB[((t + 1) * 6 + kk) * GU];
            }
        }
#pragma unroll
        for (int kk = 0; kk < 6; ++kk) {
            int k = t * 6 + kk;
            float4 y0 = *(const float4*)(yc + k * 8);
            float4 y1 = *(const float4*)(yc + k * 8 + 4);
            float w0 = wa[kk], w1 = wb[kk];
            aA[0] += y0.x * w0; aA[1] += y0.y * w0; aA[2] += y0.z * w0; aA[3] += y0.w * w0;
            aA[4] += y1.x * w0; aA[5] += y1.y * w0; aA[6] += y1.z * w0; aA[7] += y1.w * w0;
            aB[0] += y0.x * w1; aB[1] += y0.y * w1; aB[2] += y0.z * w1; aB[3] += y0.w * w1;
            aB[4] += y1.x * w1; aB[5] += y1.y * w1; aB[6] += y1.z * w1; aB[7] += y1.w * w1;
        }
        if (t + 1 < 14) {
#pragma unroll
            for (int kk = 0; kk < 6; ++kk) { wa[kk] = na[kk]; wb[kk] = nb[kk]; }
        }
    }
    float* u = pU + ks * 1600 + j * 8;
    float* rr = pR + ks * 1600 + j * 8;
    *(float4*)u        = make_float4(aA[0], aA[1], aA[2], aA[3]);
    *(float4*)(u + 4)  = make_float4(aA[4], aA[5], aA[6], aA[7]);
    *(float4*)rr       = make_float4(aB[0], aB[1], aB[2], aB[3]);
    *(float4*)(rr + 4) = make_float4(aB[4], aB[5], aB[6], aB[7]);
}

__device__ __forceinline__ void gru_l1_single_ks(const float* __restrict__ wA,
                                                 const float* __restrict__ ycT,
                                                 float* __restrict__ pN,
                                                 int j, int ks) {
    float aA[8];
#pragma unroll
    for (int r = 0; r < 8; ++r) aA[r] = 0.f;
    const float* pA = wA + (size_t)ks * KH * GU + j;
    const float* yc = ycT + ks * KH * 8;
    float wa[12];
#pragma unroll
    for (int kk = 0; kk < 12; ++kk) wa[kk] = pA[kk * GU];
#pragma unroll 1
    for (int t = 0; t < 7; ++t) {
        float na[12];
        if (t + 1 < 7) {
#pragma unroll
            for (int kk = 0; kk < 12; ++kk) na[kk] = pA[((t + 1) * 12 + kk) * GU];
        }
#pragma unroll
        for (int kk = 0; kk < 12; ++kk) {
            int k = t * 12 + kk;
            float4 y0 = *(const float4*)(yc + k * 8);
            float4 y1 = *(const float4*)(yc + k * 8 + 4);
            float w0 = wa[kk];
            aA[0] += y0.x * w0; aA[1] += y0.y * w0; aA[2] += y0.z * w0; aA[3] += y0.w * w0;
            aA[4] += y1.x * w0; aA[5] += y1.y * w0; aA[6] += y1.z * w0; aA[7] += y1.w * w0;
        }
        if (t + 1 < 7) {
#pragma unroll
            for (int kk = 0; kk < 12; ++kk) wa[kk] = na[kk];
        }
    }
    float* p = pN + ks * 1600 + j * 8;
    *(float4*)p       = make_float4(aA[0], aA[1], aA[2], aA[3]);
    *(float4*)(p + 4) = make_float4(aA[4], aA[5], aA[6], aA[7]);
}

// encoder MLP: ytmpT [20][8] -> pe [10][20][8] partials (caller combines)
__device__ __forceinline__ void enc_eval(const float* __restrict__ ew1,
                                         const float* __restrict__ eb1,
                                         const float* __restrict__ ew2,
                                         const float* __restrict__ ytmpT,
                                         float* __restrict__ hencT,
                                         float* __restrict__ pe1,
                                         float* __restrict__ pe, int tid) {
    if (tid < 200) {
        int j = tid % UNI, ks = tid / UNI;
        float a[8];
#pragma unroll
        for (int r = 0; r < 8; ++r) a[r] = 0.f;
#pragma unroll
        for (int k = ks * 10; k < ks * 10 + 10; ++k) {
            float w = ew1[k * UNI + j];
            float4 y0 = *(const float4*)(ytmpT + k * 8);
            float4 y1 = *(const float4*)(ytmpT + k * 8 + 4);
            a[0] += y0.x * w; a[1] += y0.y * w; a[2] += y0.z * w; a[3] += y0.w * w;
            a[4] += y1.x * w; a[5] += y1.y * w; a[6] += y1.z * w; a[7] += y1.w * w;
        }
        float* p = pe1 + ks * 800 + j * 8;
        *(float4*)p       = make_float4(a[0], a[1], a[2], a[3]);
        *(float4*)(p + 4) = make_float4(a[4], a[5], a[6], a[7]);
    }
    __syncthreads();
    for (int i = tid; i < 800; i += NTHR)
        hencT[i] = tanhf(pe1[i] + pe1[800 + i] + eb1[i >> 3]);
    __syncthreads();
    if (tid < 200) {
        int jj = tid % LL, ks = tid / LL;   // ks 0..9, K=10
        float a[8];
#pragma unroll
        for (int r = 0; r < 8; ++r) a[r] = 0.f;
#pragma unroll
        for (int k = ks * 10; k < ks * 10 + 10; ++k) {
            float w = ew2[k * LL + jj];
            float4 y0 = *(const float4*)(hencT + k * 8);
            float4 y1 = *(const float4*)(hencT + k * 8 + 4);
            a[0] += y0.x * w; a[1] += y0.y * w; a[2] += y0.z * w; a[3] += y0.w * w;
            a[4] += y1.x * w; a[5] += y1.y * w; a[6] += y1.z * w; a[7] += y1.w * w;
        }
        float* p = pe + ks * 160 + jj * 8;
        *(float4*)p       = make_float4(a[0], a[1], a[2], a[3]);
        *(float4*)(p + 4) = make_float4(a[4], a[5], a[6], a[7]);
    }
    __syncthreads();
}

#define ENC_K(tidv) (pe[(tidv)] + pe[160 + (tidv)] + pe[320 + (tidv)] + pe[480 + (tidv)] + \
                     pe[640 + (tidv)] + pe[800 + (tidv)] + pe[960 + (tidv)] + pe[1120 + (tidv)] + \
                     pe[1280 + (tidv)] + pe[1440 + (tidv)] + eb2[(tidv) >> 3])

// decoder MLP partials: zin [32][8] -> pd3 [10][32][8] (caller combines)
__device__ __forceinline__ void dec_eval(const float* __restrict__ dw1,
                                         const float* __restrict__ db1,
                                         const float* __restrict__ dw2,
                                         const float* __restrict__ db2,
                                         const float* __restrict__ dw3,
                                         const float* __restrict__ zin,
                                         float* __restrict__ h1T,
                                         float* __restrict__ h2T,
                                         float* __restrict__ pd1,
                                         float* __restrict__ pd2,
                                         float* __restrict__ pd3, int tid) {
    if (tid < 400) {
        int j = tid % UNI, ks = tid / UNI;   // ks 0..3, K=8
        float a[8];
#pragma unroll
        for (int r = 0; r < 8; ++r) a[r] = 0.f;
#pragma unroll
        for (int k = ks * 8; k < ks * 8 + 8; ++k) {
            float w = dw1[k * UNI + j];
            float4 z0 = *(const float4*)(zin + k * 8);
            float4 z1 = *(const float4*)(zin + k * 8 + 4);
            a[0] += z0.x * w; a[1] += z0.y * w; a[2] += z0.z * w; a[3] += z0.w * w;
            a[4] += z1.x * w; a[5] += z1.y * w; a[6] += z1.z * w; a[7] += z1.w * w;
        }
        float* p = pd1 + ks * 800 + j * 8;
        *(float4*)p       = make_float4(a[0], a[1], a[2], a[3]);
        *(float4*)(p + 4) = make_float4(a[4], a[5], a[6], a[7]);
    }
    __syncthreads();
    for (int i = tid; i < 800; i += NTHR)
        h1T[i] = tanhf(pd1[i] + pd1[800 + i] + pd1[1600 + i] + pd1[2400 + i] + db1[i >> 3]);
    __syncthreads();
    if (tid < 400) {
        int j = tid % UNI, ks = tid / UNI;   // ks 0..3, K=25
        float a[8];
#pragma unroll
        for (int r = 0; r < 8; ++r) a[r] = 0.f;
#pragma unroll 5
        for (int k = ks * 25; k < ks * 25 + 25; ++k) {
            float w = dw2[k * UNI + j];
            float4 z0 = *(const float4*)(h1T + k * 8);
            float4 z1 = *(const float4*)(h1T + k * 8 + 4);
            a[0] += z0.x * w; a[1] += z0.y * w; a[2] += z0.z * w; a[3] += z0.w * w;
            a[4] += z1.x * w; a[5] += z1.y * w; a[6] += z1.z * w; a[7] += z1.w * w;
        }
        float* p = pd2 + ks * 800 + j * 8;
        *(float4*)p       = make_float4(a[0], a[1], a[2], a[3]);
        *(float4*)(p + 4) = make_float4(a[4], a[5], a[6], a[7]);
    }
    __syncthreads();
    for (int i = tid; i < 800; i += NTHR)
        h2T[i] = tanhf(pd2[i] + pd2[800 + i] + pd2[1600 + i] + pd2[2400 + i] + db2[i >> 3]);
    __syncthreads();
    if (tid < 320) {
        int jj = tid % LATD, ks = tid / LATD;  // ks 0..9, K=10
        float a[8];
#pragma unroll
        for (int r = 0; r < 8; ++r) a[r] = 0.f;
#pragma unroll
        for (int k = ks * 10; k < ks * 10 + 10; ++k) {
            float w = dw3[k * LATD + jj];
            float4 z0 = *(const float4*)(h2T + k * 8);
            float4 z1 = *(const float4*)(h2T + k * 8 + 4);
            a[0] += z0.x * w; a[1] += z0.y * w; a[2] += z0.z * w; a[3] += z0.w * w;
            a[4] += z1.x * w; a[5] += z1.y * w; a[6] += z1.z * w; a[7] += z1.w * w;
        }
        float* p = pd3 + ks * 256 + jj * 8;
        *(float4*)p       = make_float4(a[0], a[1], a[2], a[3]);
        *(float4*)(p + 4) = make_float4(a[4], a[5], a[6], a[7]);
    }
    __syncthreads();
}

#define DEC_K(tidv) (pd3[(tidv)] + pd3[256 + (tidv)] + pd3[512 + (tidv)] + pd3[768 + (tidv)] + \
                     pd3[1024 + (tidv)] + pd3[1280 + (tidv)] + pd3[1536 + (tidv)] + pd3[1792 + (tidv)] + \
                     pd3[2048 + (tidv)] + pd3[2304 + (tidv)] + db3[(tidv) >> 3])

extern "C" __global__ void __launch_bounds__(NTHR, 1)
latent_ode_main(const float* __restrict__ truth, const float* __restrict__ tarr,
                const int* __restrict__ obs_idx, const float* __restrict__ eps,
                const float* __restrict__ ew1g, const float* __restrict__ eb1g,
                const float* __restrict__ ew2g, const float* __restrict__ eb2g,
                const float* __restrict__ uw1, const float* __restrict__ ub1g,
                const float* __restrict__ uw2g, const float* __restrict__ ub2g,
                const float* __restrict__ rw1, const float* __restrict__ rb1g,
                const float* __restrict__ rw2g, const float* __restrict__ rb2g,
                const float* __restrict__ nw1, const float* __restrict__ nb1g,
                const float* __restrict__ nw2g, const float* __restrict__ nb2g,
                const float* __restrict__ z0w1, const float* __restrict__ z0b1,
                const float* __restrict__ z0w2, const float* __restrict__ z0b2,
                const float* __restrict__ dw1g, const float* __restrict__ db1g,
                const float* __restrict__ dw2g, const float* __restrict__ db2g,
                const float* __restrict__ dw3g, const float* __restrict__ db3g,
                const float* __restrict__ owg, const float* __restrict__ obg,
                float* __restrict__ out) {
    extern __shared__ float s[];
    const int tid = threadIdx.x;
    const int b0 = blockIdx.x * ROWS;

    float* zT = s;           // [32][8] k-major, persistent
    float* P  = s + 256;

    // ---------------- encoder smem layout ----------------
    float* ew1   = P;            // 2000
    float* ew2   = P + 2000;     // 2000
    float* eb1   = P + 4000;     // 100
    float* eb2   = P + 4100;     // 20 (pad to 4128)
    float* uw2   = P + 4128;     // 8000
    float* rw2   = P + 12128;    // 8000
    float* nw2   = P + 20128;    // 8000
    float* ub1   = P + 28128;    // 200
    float* rb1   = P + 28328;    // 200
    float* nb1   = P + 28528;    // 200
    float* ub2   = P + 28728;    // 40
    float* rb2   = P + 28768;    // 40
    float* nb2   = P + 28808;    // 40
    float* csu   = P + 28848;    // 200
    float* csr   = P + 29048;    // 200
    float* csn   = P + 29248;    // 200
    float* y     = P + 29448;    // 320  [8][40]
    float* ycT   = P + 29768;    // 1344 [168][8]
    float* ytmpT = P + 31112;    // 160
    float* accT  = P + 31272;    // 160
    float* hencT = P + 31432;    // 800
    float* pe1   = P + 32232;    // 1600 [2][100][8]
    float* pe    = P + 33832;    // 1600 [10][20][8]
    float* hTa   = P + 35432;    // 1600 [200][8]
    float* hTb   = P + 37032;    // 1600
    float* pL1   = P + 38632;    // 6400 [2 gates][2 ks][200][8]
    float* p2    = P + 45032;    // 2560 [2][4][40][8]
    float* pn    = P + 47592;    // 2560 [8][40][8]
    float* u_    = P + 50152;    // 320  [8][40]
    float* r_    = P + 50472;    // 320  (end 50792)

    for (int i = tid; i < 2000; i += NTHR) { ew1[i] = ew1g[i]; ew2[i] = ew2g[i]; }
    for (int i = tid; i < 100;  i += NTHR) eb1[i] = eb1g[i];
    for (int i = tid; i < 20;   i += NTHR) eb2[i] = eb2g[i];
    for (int i = tid; i < 8000; i += NTHR) { uw2[i] = uw2g[i]; rw2[i] = rw2g[i]; nw2[i] = nw2g[i]; }
    for (int i = tid; i < 200;  i += NTHR) {
        ub1[i] = ub1g[i]; rb1[i] = rb1g[i]; nb1[i] = nb1g[i];
        csu[i] = g_colsum[i]; csr[i] = g_colsum[200 + i]; csn[i] = g_colsum[400 + i];
    }
    for (int i = tid; i < 40; i += NTHR) { ub2[i] = ub2g[i]; rb2[i] = rb2g[i]; nb2[i] = nb2g[i]; }
    for (int i = tid; i < ROWS * 40; i += NTHR) y[i] = 0.f;
    __syncthreads();

    // ================= encoder scan =================
    for (int st = 0; st < TOBS; ++st) {
        int io = obs_idx[TOBS - 1 - st];
        float dt = 0.f;
        if (st > 0) { int ip = obs_idx[TOBS - st]; dt = tarr[io] - tarr[ip]; }

        // ---- RK4 on ym ----
        if (tid < 160) { int j = tid >> 3, r = tid & 7; ytmpT[tid] = y[r * 40 + j]; }
        __syncthreads();
        enc_eval(ew1, eb1, ew2, ytmpT, hencT, pe1, pe, tid);
        if (tid < 160) {
            int j = tid >> 3, r = tid & 7;
            float kv = ENC_K(tid);
            accT[tid] = kv;
            ytmpT[tid] = y[r * 40 + j] + 0.5f * dt * kv;
        }
        __syncthreads();
        enc_eval(ew1, eb1, ew2, ytmpT, hencT, pe1, pe, tid);
        if (tid < 160) {
            int j = tid >> 3, r = tid & 7;
            float kv = ENC_K(tid);
            accT[tid] += 2.f * kv;
            ytmpT[tid] = y[r * 40 + j] + 0.5f * dt * kv;
        }
        __syncthreads();
        enc_eval(ew1, eb1, ew2, ytmpT, hencT, pe1, pe, tid);
        if (tid < 160) {
            int j = tid >> 3, r = tid & 7;
            float kv = ENC_K(tid);
            accT[tid] += 2.f * kv;
            ytmpT[tid] = y[r * 40 + j] + dt * kv;
        }
        __syncthreads();
        enc_eval(ew1, eb1, ew2, ytmpT, hencT, pe1, pe, tid);
        if (tid < 160) {
            int j = tid >> 3, r = tid & 7;
            float kv = ENC_K(tid);
            y[r * 40 + j] += dt * (1.f / 6.f) * (accT[tid] + kv);
        }
        __syncthreads();

        // ---- build ycT ----
        for (int i = tid; i < GIN * ROWS; i += NTHR) {
            int k = i >> 3, r = i & 7;
            ycT[i] = (k < 40) ? y[r * 40 + k]
                              : truth[(size_t)io * (BB * DD) + (size_t)(b0 + r) * DD + (k - 40)];
        }
        __syncthreads();

        // ---- u,r layer1 (K-split 2) ----
        if (tid < 400)
            gru_l1_dual_ks(uw1, rw1, ycT, pL1, pL1 + 3200, tid % GU, tid / GU);
        __syncthreads();
        // reduce + bias + tanh
        for (int i = tid; i < 3200; i += NTHR) {
            int g = i / 1600, rem = i % 1600, j = rem >> 3;
            float base = g ? (csr[j] + rb1[j]) : (csu[j] + ub1[j]);
            float v = pL1[g * 3200 + rem] + pL1[g * 3200 + 1600 + rem] + base;
            (g ? hTb : hTa)[rem] = tanhf(v);
        }
        __syncthreads();

        // ---- u,r layer2 (K-split 4) ----
        if (tid < 320) {
            int g = tid / 160, rem = tid % 160, jj = rem % 40, ks = rem / 40;  // K=50
            const float* hT = g ? hTb : hTa;
            const float* w2 = g ? rw2 : uw2;
            float a[8];
#pragma unroll
            for (int r = 0; r < 8; ++r) a[r] = 0.f;
#pragma unroll 10
            for (int k = ks * 50; k < ks * 50 + 50; ++k) {
                float w = w2[k * 40 + jj];
                float4 h0 = *(const float4*)(hT + k * 8);
                float4 h1 = *(const float4*)(hT + k * 8 + 4);
                a[0] += h0.x * w; a[1] += h0.y * w; a[2] += h0.z * w; a[3] += h0.w * w;
                a[4] += h1.x * w; a[5] += h1.y * w; a[6] += h1.z * w; a[7] += h1.w * w;
            }
            float* p = p2 + g * 1280 + ks * 320 + jj * 8;
            *(float4*)p       = make_float4(a[0], a[1], a[2], a[3]);
            *(float4*)(p + 4) = make_float4(a[4], a[5], a[6], a[7]);
        }
        __syncthreads();
        // reduce + sigmoid
        for (int i = tid; i < 640; i += NTHR) {
            int g = i / 320, rem = i % 320, jj = rem >> 3, r = rem & 7;
            const float* p = p2 + g * 1280;
            float a = p[rem] + p[320 + rem] + p[640 + rem] + p[960 + rem] + (g ? rb2 : ub2)[jj];
            float sg = 1.f / (1.f + expf(-a));
            (g ? r_ : u_)[r * 40 + jj] = sg;
        }
        __syncthreads();

        // ---- scale y-part of ycT by r ----
        if (tid < 320) {
            int k = tid >> 3, r = tid & 7;
            ycT[tid] *= r_[r * 40 + k];
        }
        __syncthreads();

        // ---- n layer1 (K-split 2) ----
        if (tid < 400)
            gru_l1_single_ks(nw1, ycT, pL1, tid % GU, tid / GU);
        __syncthreads();
        for (int i = tid; i < 1600; i += NTHR) {
            int j = i >> 3;
            hTa[i] = tanhf(pL1[i] + pL1[1600 + i] + csn[j] + nb1[j]);
        }
        __syncthreads();

        // ---- n layer2 (K-split 8) ----
        if (tid < 320) {
            int jj = tid % 40, ks = tid / 40;   // K=25
            float a[8];
#pragma unroll
            for (int r = 0; r < 8; ++r) a[r] = 0.f;
#pragma unroll 5
            for (int k = ks * 25; k < ks * 25 + 25; ++k) {
                float w = nw2[k * 40 + jj];
                float4 h0 = *(const float4*)(hTa + k * 8);
                float4 h1 = *(const float4*)(hTa + k * 8 + 4);
                a[0] += h0.x * w; a[1] += h0.y * w; a[2] += h0.z * w; a[3] += h0.w * w;
                a[4] += h1.x * w; a[5] += h1.y * w; a[6] += h1.z * w; a[7] += h1.w * w;
            }
            float* p = pn + ks * 320 + jj * 8;
            *(float4*)p       = make_float4(a[0], a[1], a[2], a[3]);
            *(float4*)(p + 4) = make_float4(a[4], a[5], a[6], a[7]);
        }
        __syncthreads();
        // reduce + state update
        if (tid < 320) {
            int jj = tid >> 3, r = tid & 7;
            float a = pn[tid] + pn[320 + tid] + pn[640 + tid] + pn[960 + tid]
                    + pn[1280 + tid] + pn[1600 + tid] + pn[1920 + tid] + pn[2240 + tid] + nb2[jj];
            float val = (jj < LL) ? a : fabsf(a);
            float uu = u_[r * 40 + jj];
            y[r * 40 + jj] = (1.f - uu) * val + uu * y[r * 40 + jj];
        }
        __syncthreads();
    }

    // ================= z0 head (once) =================
    for (int i = tid; i < ROWS * UNI; i += NTHR) {
        int r = i / UNI, j = i % UNI;
        float a = z0b1[j];
#pragma unroll 4
        for (int k = 0; k < 40; ++k) a += y[r * 40 + k] * z0w1[k * UNI + j];
        hencT[i] = tanhf(a);
    }
    __syncthreads();
    for (int i = tid; i < ROWS * 64; i += NTHR) {
        int r = i / 64, j = i % 64;
        float a = z0b2[j];
#pragma unroll 4
        for (int k = 0; k < UNI; ++k) a += hencT[r * UNI + k] * z0w2[k * 64 + j];
        hTa[r * 64 + j] = a;
    }
    __syncthreads();
    if (tid < 256) {
        int r = tid >> 5, j = tid & 31;
        float m = hTa[r * 64 + j];
        float sd = fabsf(hTa[r * 64 + 32 + j]);
        zT[j * 8 + r] = m + eps[(size_t)(b0 + r) * LATD + j] * sd;
    }
    __syncthreads();

    // ---------------- decoder smem layout (aliases P) ----------------
    float* dw1   = P;             // 3200
    float* dw2   = P + 3200;      // 10000
    float* dw3   = P + 13200;     // 3200
    float* db1   = P + 16400;     // 100
    float* db2   = P + 16500;     // 100
    float* db3   = P + 16600;     // 32
    float* ow    = P + 16632;     // 4096
    float* ob    = P + 20728;     // 128
    float* h1T   = P + 20856;     // 800
    float* h2T   = P + 21656;     // 800
    float* ztmpT = P + 22456;     // 256
    float* zacc  = P + 22712;     // 256
    float* pd1   = P + 22968;     // 3200
    float* pd2   = P + 26168;     // 3200
    float* pd3   = P + 29368;     // 2560
    float* pp    = P + 31928;     // 2048 [2][128][8]

    for (int i = tid; i < 3200;  i += NTHR) { dw1[i] = dw1g[i]; dw3[i] = dw3g[i]; }
    for (int i = tid; i < 10000; i += NTHR) dw2[i] = dw2g[i];
    for (int i = tid; i < 100;   i += NTHR) { db1[i] = db1g[i]; db2[i] = db2g[i]; }
    for (int i = tid; i < 32;    i += NTHR) db3[i] = db3g[i];
    for (int i = tid; i < 4096;  i += NTHR) ow[i] = owg[i];
    for (int i = tid; i < 128;   i += NTHR) ob[i] = obg[i];
    __syncthreads();

    // output projection for t = 0 (K-split 2 + reduce)
    if (tid < 256) {
        int d = tid % DD, h = tid / DD;   // K=16 per half
        float a[8];
#pragma unroll
        for (int r = 0; r < 8; ++r) a[r] = 0.f;
#pragma unroll
        for (int k = h * 16; k < h * 16 + 16; ++k) {
            float w = ow[k * DD + d];
            float4 z0 = *(const float4*)(zT + k * 8);
            float4 z1 = *(const float4*)(zT + k * 8 + 4);
            a[0] += z0.x * w; a[1] += z0.y * w; a[2] += z0.z * w; a[3] += z0.w * w;
            a[4] += z1.x * w; a[5] += z1.y * w; a[6] += z1.z * w; a[7] += z1.w * w;
        }
        float* p = pp + h * 1024 + d * 8;
        *(float4*)p       = make_float4(a[0], a[1], a[2], a[3]);
        *(float4*)(p + 4) = make_float4(a[4], a[5], a[6], a[7]);
    }
    __syncthreads();
    if (tid < DD) {
        int d = tid;
#pragma unroll
        for (int r = 0; r < 8; ++r)
            out[(size_t)(b0 + r) * (TT * DD) + d] = pp[d * 8 + r] + pp[1024 + d * 8 + r] + ob[d];
    }
    __syncthreads();

    // ================= decoder scan =================
    for (int ti = 1; ti < TT; ++ti) {
        float dt = tarr[ti] - tarr[ti - 1];

        if (tid < 256) ztmpT[tid] = zT[tid];
        __syncthreads();
        dec_eval(dw1, db1, dw2, db2, dw3, ztmpT, h1T, h2T, pd1, pd2, pd3, tid);
        if (tid < 256) {
            float kv = DEC_K(tid);
            zacc[tid] = kv;
            ztmpT[tid] = zT[tid] + 0.5f * dt * kv;
        }
        __syncthreads();
        dec_eval(dw1, db1, dw2, db2, dw3, ztmpT, h1T, h2T, pd1, pd2, pd3, tid);
        if (tid < 256) {
            float kv = DEC_K(tid);
            zacc[tid] += 2.f * kv;
            ztmpT[tid] = zT[tid] + 0.5f * dt * kv;
        }
        __syncthreads();
        dec_eval(dw1, db1, dw2, db2, dw3, ztmpT, h1T, h2T, pd1, pd2, pd3, tid);
        if (tid < 256) {
            float kv = DEC_K(tid);
            zacc[tid] += 2.f * kv;
            ztmpT[tid] = zT[tid] + dt * kv;
        }
        __syncthreads();
        dec_eval(dw1, db1, dw2, db2, dw3, ztmpT, h1T, h2T, pd1, pd2, pd3, tid);
        if (tid < 256) {
            float kv = DEC_K(tid);
            zT[tid] += dt * (1.f / 6.f) * (zacc[tid] + kv);
        }
        __syncthreads();

        // output projection (K-split 2 + reduce)
        if (tid < 256) {
            int d = tid % DD, h = tid / DD;
            float a[8];
#pragma unroll
            for (int r = 0; r < 8; ++r) a[r] = 0.f;
#pragma unroll
            for (int k = h * 16; k < h * 16 + 16; ++k) {
                float w = ow[k * DD + d];
                float4 z0 = *(const float4*)(zT + k * 8);
                float4 z1 = *(const float4*)(zT + k * 8 + 4);
                a[0] += z0.x * w; a[1] += z0.y * w; a[2] += z0.z * w; a[3] += z0.w * w;
                a[4] += z1.x * w; a[5] += z1.y * w; a[6] += z1.z * w; a[7] += z1.w * w;
            }
            float* p = pp + h * 1024 + d * 8;
            *(float4*)p       = make_float4(a[0], a[1], a[2], a[3]);
            *(float4*)(p + 4) = make_float4(a[4], a[5], a[6], a[7]);
        }
        __syncthreads();
        if (tid < DD) {
            int d = tid;
#pragma unroll
            for (int r = 0; r < 8; ++r)
                out[(size_t)(b0 + r) * (TT * DD) + (size_t)ti * DD + d] =
                    pp[d * 8 + r] + pp[1024 + d * 8 + r] + ob[d];
        }
        __syncthreads();
    }
}

extern "C" void kernel_launch(void* const* d_in, const int* in_sizes, int n_in,
                              void* d_out, int out_size) {
    (void)in_sizes; (void)n_in; (void)out_size;
    size_t smem = (size_t)SM_FLOATS * sizeof(float);
    cudaFuncSetAttribute(latent_ode_main, cudaFuncAttributeMaxDynamicSharedMemorySize, (int)smem);

    colsum_kernel<<<3, GU>>>((const float*)d_in[8], (const float*)d_in[12], (const float*)d_in[16]);

    latent_ode_main<<<NBLK, NTHR, smem>>>(
        (const float*)d_in[0], (const float*)d_in[1], (const int*)d_in[2], (const float*)d_in[3],
        (const float*)d_in[4],  (const float*)d_in[5],  (const float*)d_in[6],  (const float*)d_in[7],
        (const float*)d_in[8],  (const float*)d_in[9],  (const float*)d_in[10], (const float*)d_in[11],
        (const float*)d_in[12], (const float*)d_in[13], (const float*)d_in[14], (const float*)d_in[15],
        (const float*)d_in[16], (const float*)d_in[17], (const float*)d_in[18], (const float*)d_in[19],
        (const float*)d_in[20], (const float*)d_in[21], (const float*)d_in[22], (const float*)d_in[23],
        (const float*)d_in[24], (const float*)d_in[25], (const float*)d_in[26], (const float*)d_in[27],
        (const float*)d_in[28], (const float*)d_in[29], (const float*)d_in[30], (const float*)d_in[31],
        (float*)d_out);
}